// round 7
// baseline (speedup 1.0000x reference)
#include <cuda_runtime.h>
#include <cuda_fp16.h>
#include <math.h>
#include <stdint.h>

#define B_ROWS 16384
#define D_DIM  2048
#define H_DIM  512
#define NCHUNK 8          // 512 / 64
#define LO_SCALE   2048.0f          // 2^11
#define LO_INV     4.8828125e-4f    // 2^-11

// ------------------------- device scratch -------------------------
__device__ __half g_ws[2ull * H_DIM * D_DIM];    // W1^T split hi / scaled-lo [H,D]
__device__ float  g_partial[B_ROWS * NCHUNK];
__device__ int    g_k[B_ROWS];
__device__ float  g_l1row[B_ROWS];

// ------------------------- helpers --------------------------------
__device__ __forceinline__ uint32_t smem_u32(const void* p) {
    uint32_t a;
    asm("{ .reg .u64 t; cvta.to.shared.u64 t, %1; cvt.u32.u64 %0, t; }" : "=r"(a) : "l"(p));
    return a;
}
__device__ __forceinline__ uint32_t swz128(uint32_t b) { return b ^ ((b >> 3) & 0x70u); }

__device__ __forceinline__ void cp16(uint32_t dst, const void* src) {
    asm volatile("cp.async.cg.shared.global [%0], [%1], 16;" :: "r"(dst), "l"(src) : "memory");
}
__device__ __forceinline__ void cp_commit() {
    asm volatile("cp.async.commit_group;" ::: "memory");
}
template <int N>
__device__ __forceinline__ void cp_wait() {
    asm volatile("cp.async.wait_group %0;" :: "n"(N) : "memory");
}
__device__ __forceinline__ void ldsm4(uint32_t* r, uint32_t addr) {
    asm volatile("ldmatrix.sync.aligned.m8n8.x4.shared.b16 {%0,%1,%2,%3}, [%4];"
                 : "=r"(r[0]), "=r"(r[1]), "=r"(r[2]), "=r"(r[3]) : "r"(addr));
}
__device__ __forceinline__ void mma16816(float* c, const uint32_t* a,
                                         uint32_t b0, uint32_t b1) {
    asm volatile(
        "mma.sync.aligned.m16n8k16.row.col.f32.f16.f16.f32 "
        "{%0,%1,%2,%3}, {%4,%5,%6,%7}, {%8,%9}, {%0,%1,%2,%3};"
        : "+f"(c[0]), "+f"(c[1]), "+f"(c[2]), "+f"(c[3])
        : "r"(a[0]), "r"(a[1]), "r"(a[2]), "r"(a[3]), "r"(b0), "r"(b1));
}

__device__ __forceinline__ void split2s(float f, __half& h, __half& l) {
    h = __float2half_rn(f);
    l = __float2half_rn((f - __half2float(h)) * LO_SCALE);   // scaled: stays normal
}

// --------------- stage 0: split + transpose W1 ---------------------
__global__ void __launch_bounds__(256) convert_w1(const float* __restrict__ W1)
{
    size_t idx = (size_t)blockIdx.x * 256 + threadIdx.x;   // over [D, H]
    if (idx >= (size_t)D_DIM * H_DIM) return;
    int k = (int)(idx / H_DIM);
    int n = (int)(idx % H_DIM);
    __half h, l;
    split2s(W1[idx], h, l);
    const size_t P = (size_t)H_DIM * D_DIM;
    size_t o = (size_t)n * D_DIM + k;
    g_ws[o]     = h;
    g_ws[P + o] = l;
}

// --------------- stage 1: HMMA split-2 GEMM, fused x-convert -------
// CTA tile: 128(M) x 64(N), BK=64. Grid (8 n-tiles, 128 m-tiles).
// A: fp32 x loaded to regs, split in-kernel to 2 fp16 smem planes.
// smem: A 2stage x 2plane x 16KB = 64KB; B 2stage x 2plane x 8KB = 32KB.
#define SM_DYN (98304 + 1024)

__global__ void __launch_bounds__(256, 1) gemm_predictor(
    const float* __restrict__ x,
    const float* __restrict__ b1, const float* __restrict__ W2)
{
    extern __shared__ char smem_raw[];
    __shared__ float red[128][4];

    const uint32_t sb  = (smem_u32(smem_raw) + 1023u) & ~1023u;
    const uint32_t sbB = sb + 65536u;
    const int tid  = threadIdx.x;
    const int lane = tid & 31;
    const int w    = tid >> 5;
    const int wm   = w >> 2;          // 0..1  (M64 rows)
    const int wn   = w & 3;           // 0..3  (N16 cols)
    const int m0   = blockIdx.y * 128;
    const int n0   = blockIdx.x * 64;
    const size_t PW = (size_t)H_DIM * D_DIM;

    // A staging: this thread owns row (tid>>1), cols [32*(tid&1), +32)
    const int arow = tid >> 1;
    const int acol = (tid & 1) * 32;
    const float* aptr = x + (size_t)(m0 + arow) * D_DIM + acol;

    float chi[4][2][4];   // hh
    float clo[4][2][4];   // hl + lh (scaled by 2^11)
#pragma unroll
    for (int i = 0; i < 4; i++)
#pragma unroll
        for (int j = 0; j < 2; j++)
#pragma unroll
            for (int e = 0; e < 4; e++) { chi[i][j][e] = 0.f; clo[i][j][e] = 0.f; }

    float4 areg[8];       // 32 fp32 staged for next stage

    auto loadA_regs = [&](int kt) {
        const float* p = aptr + kt * 64;
#pragma unroll
        for (int j = 0; j < 8; ++j)
            areg[j] = *reinterpret_cast<const float4*>(p + j * 4);
    };
    auto storeA_smem = [&](int stage) {
        const uint32_t Ah = sb + (uint32_t)(stage * 2 + 0) * 16384u;
        const uint32_t Al = sb + (uint32_t)(stage * 2 + 1) * 16384u;
        __half hh[32], ll[32];
#pragma unroll
        for (int j = 0; j < 8; ++j) {
            split2s(areg[j].x, hh[j*4+0], ll[j*4+0]);
            split2s(areg[j].y, hh[j*4+1], ll[j*4+1]);
            split2s(areg[j].z, hh[j*4+2], ll[j*4+2]);
            split2s(areg[j].w, hh[j*4+3], ll[j*4+3]);
        }
#pragma unroll
        for (int j = 0; j < 4; ++j) {   // 4 x 16B chunks per plane
            uint32_t off = swz128((uint32_t)(arow * 128 + acol * 2 + j * 16));
            *reinterpret_cast<uint4*>(
                reinterpret_cast<char*>(smem_raw) + (Ah - smem_u32(smem_raw)) + off) =
                *reinterpret_cast<uint4*>(&hh[j * 8]);
            *reinterpret_cast<uint4*>(
                reinterpret_cast<char*>(smem_raw) + (Al - smem_u32(smem_raw)) + off) =
                *reinterpret_cast<uint4*>(&ll[j * 8]);
        }
    };

    auto loadB = [&](int stage, int kt) {
        const int k0 = kt * 64;
#pragma unroll
        for (int p = 0; p < 2; ++p) {
            const __half* bsrc = g_ws + (size_t)p * PW;
            const uint32_t bbase = sbB + (uint32_t)(stage * 2 + p) * 8192u;
#pragma unroll
            for (int i = 0; i < 2; ++i) {          // B: 64 rows
                int u = tid + i * 256;
                int row = u >> 3, cc = u & 7;
                uint32_t soff = swz128((uint32_t)(row * 128 + cc * 16));
                cp16(bbase + soff, bsrc + (size_t)(n0 + row) * D_DIM + k0 + cc * 8);
            }
        }
    };

    auto compute = [&](int stage) {
        const uint32_t A0 = sb  + (uint32_t)(stage * 2 + 0) * 16384u;
        const uint32_t A1 = sb  + (uint32_t)(stage * 2 + 1) * 16384u;
        const uint32_t B0 = sbB + (uint32_t)(stage * 2 + 0) * 8192u;
        const uint32_t B1 = sbB + (uint32_t)(stage * 2 + 1) * 8192u;
#pragma unroll
        for (int s = 0; s < 4; ++s) {
            const int chunk = (s * 2 + (lane >> 4)) * 16;
            uint32_t brh[4], brl[4];
            {
                int row = wn * 16 + (lane & 15);
                uint32_t off = swz128((uint32_t)(row * 128 + chunk));
                ldsm4(brh, B0 + off);
                ldsm4(brl, B1 + off);
            }
#pragma unroll
            for (int mt = 0; mt < 4; ++mt) {
                int row = wm * 64 + mt * 16 + (lane & 15);
                uint32_t off = swz128((uint32_t)(row * 128 + chunk));
                uint32_t ah[4], al[4];
                ldsm4(ah, A0 + off);
                ldsm4(al, A1 + off);
#pragma unroll
                for (int nt = 0; nt < 2; ++nt) {
                    const uint32_t bh0 = brh[nt], bh1 = brh[nt + 2];
                    const uint32_t bl0 = brl[nt], bl1 = brl[nt + 2];
                    mma16816(chi[mt][nt], ah, bh0, bh1);   // hh
                    mma16816(clo[mt][nt], ah, bl0, bl1);   // hl (x2^11)
                    mma16816(clo[mt][nt], al, bh0, bh1);   // lh (x2^11)
                }
            }
        }
    };

    // prologue
    loadA_regs(0);
    loadB(0, 0);
    cp_commit();

    for (int kt = 0; kt < 32; ++kt) {
        storeA_smem(kt & 1);              // convert staged A(kt) into smem
        if (kt + 1 < 32) {
            loadA_regs(kt + 1);           // LDG next A (latency hidden by MMA)
            loadB((kt + 1) & 1, kt + 1);
            cp_commit();
            cp_wait<1>();
        } else {
            cp_wait<0>();
        }
        __syncthreads();
        compute(kt & 1);
        __syncthreads();
    }

    // epilogue: relu((chi + clo*2^-11) + b1) dot W2 over 64 cols -> partial
#pragma unroll
    for (int mt = 0; mt < 4; ++mt) {
#pragma unroll
        for (int h = 0; h < 2; ++h) {
            float p = 0.f;
#pragma unroll
            for (int nt = 0; nt < 2; ++nt)
#pragma unroll
                for (int e = 0; e < 2; ++e) {
                    int col = n0 + wn * 16 + nt * 8 + (lane & 3) * 2 + e;
                    float v = fmaf(clo[mt][nt][h * 2 + e], LO_INV,
                                   chi[mt][nt][h * 2 + e]) + b1[col];
                    v = fmaxf(v, 0.f);
                    p = fmaf(v, W2[col], p);
                }
            p += __shfl_xor_sync(0xffffffffu, p, 1);
            p += __shfl_xor_sync(0xffffffffu, p, 2);
            if ((lane & 3) == 0) {
                int row = wm * 64 + mt * 16 + (lane >> 2) + 8 * h;
                red[row][wn] = p;
            }
        }
    }
    __syncthreads();
    if (tid < 128) {
        float s = red[tid][0] + red[tid][1] + red[tid][2] + red[tid][3];
        g_partial[(size_t)(m0 + tid) * NCHUNK + blockIdx.x] = s;
    }
}

// ---------------- stage 2: logits -> sparsity, k -------------------
__global__ void sparsity_kernel(const float* __restrict__ b2,
                                float* __restrict__ out_sp)
{
    int b = blockIdx.x * 256 + threadIdx.x;
    if (b >= B_ROWS) return;
    float s = b2[0];
#pragma unroll
    for (int cc = 0; cc < NCHUNK; cc++) s += g_partial[(size_t)b * NCHUNK + cc];
    float sig = 1.f / (1.f + expf(-s));
    float sp  = 0.05f + 0.25f * sig;
    out_sp[b] = sp;
    int k = (int)rintf((float)D_DIM * (1.f - sp));   // round half-even
    g_k[b] = (k < 1) ? 1 : k;
}

// ---------------- stage 3: exact radix select, 3 passes ------------
__global__ void __launch_bounds__(256) select_mask_kernel(
    const float* __restrict__ x,
    float* __restrict__ out_sparse, float* __restrict__ out_mask,
    float* __restrict__ out_act)
{
    __shared__ float        xs[D_DIM];
    __shared__ unsigned int hist[2048];
    __shared__ unsigned int wsum[8];
    __shared__ float        wl1[8];
    __shared__ unsigned int wcnt[8];
    __shared__ unsigned int s_prefix, s_kk;

    const int row  = blockIdx.x;
    const int tid  = threadIdx.x;
    const int lane = tid & 31;
    const int wid  = tid >> 5;
    const float* xr = x + (size_t)row * D_DIM;

#pragma unroll
    for (int p = 0; p < 2; p++) {
        int i4 = (tid + p * 256) * 4;
        *reinterpret_cast<float4*>(&xs[i4]) =
            *reinterpret_cast<const float4*>(&xr[i4]);
    }
    if (tid == 0) { s_prefix = 0u; s_kk = (unsigned int)g_k[row]; }
#pragma unroll
    for (int z = 0; z < 8; z++) hist[tid + z * 256] = 0u;
    __syncthreads();

    const int SHIFTS[3] = {21, 10, 0};
    const int NBITS[3]  = {11, 11, 10};
#pragma unroll
    for (int ps = 0; ps < 3; ps++) {
        const int shift = SHIFTS[ps];
        const int nb    = 1 << NBITS[ps];
        const int bpt   = nb >> 8;             // bins per thread: 8,8,4
        const unsigned int prefix = s_prefix;
        const unsigned int kcur   = s_kk;
        const unsigned int himask =
            (shift + NBITS[ps] >= 32) ? 0u : (0xFFFFFFFFu << (shift + NBITS[ps]));
#pragma unroll
        for (int i = 0; i < 8; i++) {
            unsigned int key = __float_as_uint(fabsf(xs[tid + i * 256]));
            if ((key & himask) == prefix)
                atomicAdd(&hist[(key >> shift) & (nb - 1)], 1u);
        }
        __syncthreads();
        unsigned int own = 0;
#pragma unroll
        for (int j = 0; j < 8; j++)
            if (j < bpt) own += hist[tid * bpt + j];
        // block inclusive scan of per-thread sums
        unsigned int v = own;
#pragma unroll
        for (int off = 1; off < 32; off <<= 1) {
            unsigned int t = __shfl_up_sync(0xffffffffu, v, off);
            if (lane >= off) v += t;
        }
        if (lane == 31) wsum[wid] = v;
        __syncthreads();
        if (tid < 8) {
            unsigned int ws = wsum[tid];
#pragma unroll
            for (int off = 1; off < 8; off <<= 1) {
                unsigned int t = __shfl_up_sync(0xffu, ws, off, 8);
                if (tid >= off) ws += t;
            }
            wsum[tid] = ws;
        }
        __syncthreads();
        unsigned int running = v + (wid ? wsum[wid - 1] : 0u) - own;  // exclusive
        if (running < kcur && running + own >= kcur) {
#pragma unroll
            for (int j = 0; j < 8; j++) {
                if (j < bpt) {
                    unsigned int c = hist[tid * bpt + j];
                    if (running < kcur && running + c >= kcur) {
                        s_prefix = prefix | ((unsigned int)(tid * bpt + j) << shift);
                        s_kk     = kcur - running;
                    }
                    running += c;
                }
            }
        }
        __syncthreads();
#pragma unroll
        for (int z = 0; z < 8; z++) hist[tid + z * 256] = 0u;
        __syncthreads();         // publishes s_prefix / s_kk, hist clean
    }

    const float thr = __uint_as_float(s_prefix);

    unsigned int cnt = 0;
    float l1 = 0.f;
#pragma unroll
    for (int p = 0; p < 2; p++) {
        int i4 = (tid + p * 256) * 4;
        float4 v = *reinterpret_cast<const float4*>(&xs[i4]);
        float4 mk, sx;
        float ax = fabsf(v.x), ay = fabsf(v.y), az = fabsf(v.z), aw = fabsf(v.w);
        bool mx = ax > thr, my = ay > thr, mz = az > thr, mw = aw > thr;
        mk.x = mx ? 1.f : 0.f; sx.x = mx ? v.x : 0.f; if (mx) { cnt++; l1 += ax; }
        mk.y = my ? 1.f : 0.f; sx.y = my ? v.y : 0.f; if (my) { cnt++; l1 += ay; }
        mk.z = mz ? 1.f : 0.f; sx.z = mz ? v.z : 0.f; if (mz) { cnt++; l1 += az; }
        mk.w = mw ? 1.f : 0.f; sx.w = mw ? v.w : 0.f; if (mw) { cnt++; l1 += aw; }
        *reinterpret_cast<float4*>(&out_mask  [(size_t)row * D_DIM + i4]) = mk;
        *reinterpret_cast<float4*>(&out_sparse[(size_t)row * D_DIM + i4]) = sx;
    }
#pragma unroll
    for (int off = 16; off > 0; off >>= 1) {
        cnt += __shfl_xor_sync(0xffffffffu, cnt, off);
        l1  += __shfl_xor_sync(0xffffffffu, l1, off);
    }
    if (lane == 0) { wcnt[wid] = cnt; wl1[wid] = l1; }
    __syncthreads();
    if (tid == 0) {
        unsigned int c = 0; float s = 0.f;
#pragma unroll
        for (int wz = 0; wz < 8; wz++) { c += wcnt[wz]; s += wl1[wz]; }
        out_act[row] = (float)c / (float)D_DIM;
        g_l1row[row] = s;
    }
}

// ---------------- stage 4: deterministic l1 mean -------------------
__global__ void __launch_bounds__(1024) l1_reduce(float* __restrict__ out_l1)
{
    __shared__ float sm[1024];
    const int tid = threadIdx.x;
    float s = 0.f;
    for (int i = tid; i < B_ROWS; i += 1024) s += g_l1row[i];
    sm[tid] = s;
    __syncthreads();
    for (int off = 512; off > 0; off >>= 1) {
        if (tid < off) sm[tid] += sm[tid + off];
        __syncthreads();
    }
    if (tid == 0) out_l1[0] = sm[0] / (float)B_ROWS;
}

// ---------------- launch ------------------------------------------
extern "C" void kernel_launch(void* const* d_in, const int* in_sizes, int n_in,
                              void* d_out, int out_size)
{
    const float* x  = (const float*)d_in[0];
    const float* W1 = (const float*)d_in[1];
    const float* b1 = (const float*)d_in[2];
    const float* W2 = (const float*)d_in[3];
    const float* b2 = (const float*)d_in[4];

    float* out        = (float*)d_out;
    float* out_sparse = out;                                   // [B, D]
    float* out_mask   = out + (size_t)B_ROWS * D_DIM;          // [B, D]
    float* out_sp     = out + 2 * (size_t)B_ROWS * D_DIM;      // [B, 1]
    float* out_act    = out_sp + B_ROWS;                       // [B]
    float* out_l1     = out_act + B_ROWS;                      // [1]

    cudaFuncSetAttribute(gemm_predictor,
                         cudaFuncAttributeMaxDynamicSharedMemorySize, SM_DYN);

    convert_w1<<<((size_t)D_DIM * H_DIM) / 256, 256>>>(W1);
    gemm_predictor<<<dim3(8, 128), 256, SM_DYN>>>(x, b1, W2);
    sparsity_kernel<<<B_ROWS / 256, 256>>>(b2, out_sp);
    select_mask_kernel<<<B_ROWS, 256>>>(x, out_sparse, out_mask, out_act);
    l1_reduce<<<1, 1024>>>(out_l1);
}

// round 8
// speedup vs baseline: 1.2257x; 1.2257x over previous
#include <cuda_runtime.h>
#include <cuda_fp16.h>
#include <math.h>
#include <stdint.h>

#define B_ROWS 16384
#define D_DIM  2048
#define H_DIM  512
#define NCHUNK 4          // 512 / 128
#define LO_SCALE   2048.0f          // 2^11
#define LO_INV     4.8828125e-4f    // 2^-11

// ------------------------- device scratch -------------------------
__device__ __half g_xs[2ull * B_ROWS * D_DIM];   // x split hi / scaled-lo
__device__ __half g_ws[2ull * H_DIM * D_DIM];    // W1^T split hi / scaled-lo [H,D]
__device__ float  g_partial[B_ROWS * NCHUNK];
__device__ float  g_l1row[B_ROWS];

// ------------------------- helpers --------------------------------
__device__ __forceinline__ uint32_t smem_u32(const void* p) {
    uint32_t a;
    asm("{ .reg .u64 t; cvta.to.shared.u64 t, %1; cvt.u32.u64 %0, t; }" : "=r"(a) : "l"(p));
    return a;
}
__device__ __forceinline__ uint32_t swz128(uint32_t b) { return b ^ ((b >> 3) & 0x70u); }

__device__ __forceinline__ void cp16(uint32_t dst, const void* src) {
    asm volatile("cp.async.cg.shared.global [%0], [%1], 16;" :: "r"(dst), "l"(src) : "memory");
}
__device__ __forceinline__ void cp_commit() {
    asm volatile("cp.async.commit_group;" ::: "memory");
}
template <int N>
__device__ __forceinline__ void cp_wait() {
    asm volatile("cp.async.wait_group %0;" :: "n"(N) : "memory");
}
__device__ __forceinline__ void ldsm4(uint32_t* r, uint32_t addr) {
    asm volatile("ldmatrix.sync.aligned.m8n8.x4.shared.b16 {%0,%1,%2,%3}, [%4];"
                 : "=r"(r[0]), "=r"(r[1]), "=r"(r[2]), "=r"(r[3]) : "r"(addr));
}
__device__ __forceinline__ void mma16816(float* c, const uint32_t* a,
                                         uint32_t b0, uint32_t b1) {
    asm volatile(
        "mma.sync.aligned.m16n8k16.row.col.f32.f16.f16.f32 "
        "{%0,%1,%2,%3}, {%4,%5,%6,%7}, {%8,%9}, {%0,%1,%2,%3};"
        : "+f"(c[0]), "+f"(c[1]), "+f"(c[2]), "+f"(c[3])
        : "r"(a[0]), "r"(a[1]), "r"(a[2]), "r"(a[3]), "r"(b0), "r"(b1));
}

__device__ __forceinline__ void split2s(float f, __half& h, __half& l) {
    h = __float2half_rn(f);
    l = __float2half_rn((f - __half2float(h)) * LO_SCALE);   // scaled: stays normal
}

// --------------- stage 0a: split x into hi / scaled-lo -------------
__global__ void __launch_bounds__(256) convert_x(const float* __restrict__ x)
{
    size_t i4 = ((size_t)blockIdx.x * 256 + threadIdx.x) * 4;
    if (i4 >= (size_t)B_ROWS * D_DIM) return;
    float4 v = *reinterpret_cast<const float4*>(x + i4);
    __half h[4], l[4];
    split2s(v.x, h[0], l[0]);
    split2s(v.y, h[1], l[1]);
    split2s(v.z, h[2], l[2]);
    split2s(v.w, h[3], l[3]);
    const size_t P = (size_t)B_ROWS * D_DIM;
    *reinterpret_cast<uint2*>(&g_xs[i4])     = *reinterpret_cast<uint2*>(h);
    *reinterpret_cast<uint2*>(&g_xs[P + i4]) = *reinterpret_cast<uint2*>(l);
}

// --------------- stage 0b: split + transpose W1 --------------------
__global__ void __launch_bounds__(256) convert_w1(const float* __restrict__ W1)
{
    size_t idx = (size_t)blockIdx.x * 256 + threadIdx.x;   // over [D, H]
    if (idx >= (size_t)D_DIM * H_DIM) return;
    int k = (int)(idx / H_DIM);
    int n = (int)(idx % H_DIM);
    __half h, l;
    split2s(W1[idx], h, l);
    const size_t P = (size_t)H_DIM * D_DIM;
    size_t o = (size_t)n * D_DIM + k;
    g_ws[o]     = h;
    g_ws[P + o] = l;
}

// --------------- stage 1: HMMA split-2 GEMM + fused epilogue -------
// CTA tile: 128(M) x 128(N), BK=64. Grid (4 n-tiles, 128 m-tiles).
#define SM_DYN (131072 + 1024)

__global__ void __launch_bounds__(256, 1) gemm_predictor(
    const float* __restrict__ b1, const float* __restrict__ W2)
{
    extern __shared__ char smem_raw[];
    __shared__ float red[128][4];

    const uint32_t sb = (smem_u32(smem_raw) + 1023u) & ~1023u;
    const int tid  = threadIdx.x;
    const int lane = tid & 31;
    const int w    = tid >> 5;
    const int wm   = w >> 2;          // 0..1
    const int wn   = w & 3;           // 0..3
    const int m0   = blockIdx.y * 128;
    const int n0   = blockIdx.x * 128;
    const size_t PX = (size_t)B_ROWS * D_DIM;
    const size_t PW = (size_t)H_DIM * D_DIM;

    float chi[4][4][4];   // hh
    float clo[4][4][4];   // hl + lh (scaled by 2^11)
#pragma unroll
    for (int i = 0; i < 4; i++)
#pragma unroll
        for (int j = 0; j < 4; j++)
#pragma unroll
            for (int e = 0; e < 4; e++) { chi[i][j][e] = 0.f; clo[i][j][e] = 0.f; }

    auto load_tiles = [&](int stage, int kt) {
        const int k0 = kt * 64;
#pragma unroll
        for (int p = 0; p < 2; ++p) {
            const __half* asrc = g_xs + (size_t)p * PX;
            const __half* bsrc = g_ws + (size_t)p * PW;
            const uint32_t abase = sb + (uint32_t)(stage * 2 + p) * 16384u;
            const uint32_t bbase = sb + 65536u + (uint32_t)(stage * 2 + p) * 16384u;
#pragma unroll
            for (int i = 0; i < 4; ++i) {
                int u = tid + i * 256;
                int row = u >> 3, cc = u & 7;
                uint32_t soff = swz128((uint32_t)(row * 128 + cc * 16));
                cp16(abase + soff, asrc + (size_t)(m0 + row) * D_DIM + k0 + cc * 8);
                cp16(bbase + soff, bsrc + (size_t)(n0 + row) * D_DIM + k0 + cc * 8);
            }
        }
    };

    auto compute = [&](int stage) {
        const uint32_t A0 = sb + (uint32_t)(stage * 2 + 0) * 16384u;
        const uint32_t A1 = sb + (uint32_t)(stage * 2 + 1) * 16384u;
        const uint32_t B0 = sb + 65536u + (uint32_t)(stage * 2 + 0) * 16384u;
        const uint32_t B1 = sb + 65536u + (uint32_t)(stage * 2 + 1) * 16384u;
#pragma unroll
        for (int s = 0; s < 4; ++s) {
            const int chunk = (s * 2 + (lane >> 4)) * 16;
            uint32_t br[2][2][4];
#pragma unroll
            for (int np = 0; np < 2; ++np) {
                int row = wn * 32 + np * 16 + (lane & 15);
                uint32_t off = swz128((uint32_t)(row * 128 + chunk));
                ldsm4(br[0][np], B0 + off);
                ldsm4(br[1][np], B1 + off);
            }
#pragma unroll
            for (int mt = 0; mt < 4; ++mt) {
                int row = wm * 64 + mt * 16 + (lane & 15);
                uint32_t off = swz128((uint32_t)(row * 128 + chunk));
                uint32_t ah[4], al[4];
                ldsm4(ah, A0 + off);
                ldsm4(al, A1 + off);
#pragma unroll
                for (int nt = 0; nt < 4; ++nt) {
                    const int np = nt >> 1, hb = nt & 1;
                    const uint32_t bh0 = br[0][np][hb], bh1 = br[0][np][hb + 2];
                    const uint32_t bl0 = br[1][np][hb], bl1 = br[1][np][hb + 2];
                    mma16816(chi[mt][nt], ah, bh0, bh1);   // hh
                    mma16816(clo[mt][nt], ah, bl0, bl1);   // hl (x2^11)
                    mma16816(clo[mt][nt], al, bh0, bh1);   // lh (x2^11)
                }
            }
        }
    };

    load_tiles(0, 0);
    cp_commit();
    for (int kt = 0; kt < 32; ++kt) {
        if (kt + 1 < 32) {
            load_tiles((kt + 1) & 1, kt + 1);
            cp_commit();
            cp_wait<1>();
        } else {
            cp_wait<0>();
        }
        __syncthreads();
        compute(kt & 1);
        __syncthreads();
    }

    // epilogue: relu((chi + clo*2^-11) + b1) dot W2 -> partial
#pragma unroll
    for (int mt = 0; mt < 4; ++mt) {
#pragma unroll
        for (int h = 0; h < 2; ++h) {
            float p = 0.f;
#pragma unroll
            for (int nt = 0; nt < 4; ++nt)
#pragma unroll
                for (int e = 0; e < 2; ++e) {
                    int col = n0 + wn * 32 + nt * 8 + (lane & 3) * 2 + e;
                    float v = fmaf(clo[mt][nt][h * 2 + e], LO_INV,
                                   chi[mt][nt][h * 2 + e]) + b1[col];
                    v = fmaxf(v, 0.f);
                    p = fmaf(v, W2[col], p);
                }
            p += __shfl_xor_sync(0xffffffffu, p, 1);
            p += __shfl_xor_sync(0xffffffffu, p, 2);
            if ((lane & 3) == 0) {
                int row = wm * 64 + mt * 16 + (lane >> 2) + 8 * h;
                red[row][wn] = p;
            }
        }
    }
    __syncthreads();
    if (tid < 128) {
        float s = red[tid][0] + red[tid][1] + red[tid][2] + red[tid][3];
        g_partial[(size_t)(m0 + tid) * NCHUNK + blockIdx.x] = s;
    }
}

// ------- stage 2: fused sparsity + exact radix select (reg-resident) -------
__global__ void __launch_bounds__(256) select_mask_kernel(
    const float* __restrict__ x, const float* __restrict__ b2,
    float* __restrict__ out_sp,
    float* __restrict__ out_sparse, float* __restrict__ out_mask,
    float* __restrict__ out_act)
{
    __shared__ unsigned int hist[2048];
    __shared__ unsigned int wsum[8];
    __shared__ float        wl1[8];
    __shared__ unsigned int wcnt[8];
    __shared__ unsigned int s_prefix, s_kk;

    const int row  = blockIdx.x;
    const int tid  = threadIdx.x;
    const int lane = tid & 31;
    const int wid  = tid >> 5;
    const float* xr = x + (size_t)row * D_DIM;

    // x register-resident: this thread owns 8 elements (2 x float4, coalesced)
    float4 v0 = *reinterpret_cast<const float4*>(&xr[tid * 4]);
    float4 v1 = *reinterpret_cast<const float4*>(&xr[1024 + tid * 4]);
    unsigned int key[8];
    key[0] = __float_as_uint(fabsf(v0.x));
    key[1] = __float_as_uint(fabsf(v0.y));
    key[2] = __float_as_uint(fabsf(v0.z));
    key[3] = __float_as_uint(fabsf(v0.w));
    key[4] = __float_as_uint(fabsf(v1.x));
    key[5] = __float_as_uint(fabsf(v1.y));
    key[6] = __float_as_uint(fabsf(v1.z));
    key[7] = __float_as_uint(fabsf(v1.w));

    if (tid == 0) {
        // inline sparsity predictor tail: sum partials -> sigmoid -> k
        float s = b2[0];
#pragma unroll
        for (int cc = 0; cc < NCHUNK; cc++) s += g_partial[(size_t)row * NCHUNK + cc];
        float sig = 1.f / (1.f + expf(-s));
        float sp  = 0.05f + 0.25f * sig;
        out_sp[row] = sp;
        int k = (int)rintf((float)D_DIM * (1.f - sp));   // round half-even
        s_prefix = 0u;
        s_kk = (unsigned int)((k < 1) ? 1 : k);
    }
#pragma unroll
    for (int z = 0; z < 8; z++) hist[tid + z * 256] = 0u;
    __syncthreads();

    const int SHIFTS[3] = {21, 10, 0};
    const int NBITS[3]  = {11, 11, 10};
#pragma unroll
    for (int ps = 0; ps < 3; ps++) {
        const int shift = SHIFTS[ps];
        const int nb    = 1 << NBITS[ps];
        const int bpt   = nb >> 8;             // bins per thread: 8,8,4
        const unsigned int prefix = s_prefix;
        const unsigned int kcur   = s_kk;
        const unsigned int himask =
            (shift + NBITS[ps] >= 32) ? 0u : (0xFFFFFFFFu << (shift + NBITS[ps]));
#pragma unroll
        for (int i = 0; i < 8; i++) {
            if ((key[i] & himask) == prefix)
                atomicAdd(&hist[(key[i] >> shift) & (nb - 1)], 1u);
        }
        __syncthreads();
        unsigned int own = 0;
#pragma unroll
        for (int j = 0; j < 8; j++)
            if (j < bpt) own += hist[tid * bpt + j];
        // block inclusive scan of per-thread sums
        unsigned int v = own;
#pragma unroll
        for (int off = 1; off < 32; off <<= 1) {
            unsigned int t = __shfl_up_sync(0xffffffffu, v, off);
            if (lane >= off) v += t;
        }
        if (lane == 31) wsum[wid] = v;
        __syncthreads();
        if (tid < 8) {
            unsigned int ws = wsum[tid];
#pragma unroll
            for (int off = 1; off < 8; off <<= 1) {
                unsigned int t = __shfl_up_sync(0xffu, ws, off, 8);
                if (tid >= off) ws += t;
            }
            wsum[tid] = ws;
        }
        __syncthreads();
        unsigned int running = v + (wid ? wsum[wid - 1] : 0u) - own;  // exclusive
        if (running < kcur && running + own >= kcur) {
#pragma unroll
            for (int j = 0; j < 8; j++) {
                if (j < bpt) {
                    unsigned int c = hist[tid * bpt + j];
                    if (running < kcur && running + c >= kcur) {
                        s_prefix = prefix | ((unsigned int)(tid * bpt + j) << shift);
                        s_kk     = kcur - running;
                    }
                    running += c;
                }
            }
        }
        __syncthreads();
#pragma unroll
        for (int z = 0; z < 8; z++) hist[tid + z * 256] = 0u;
        __syncthreads();         // publishes s_prefix / s_kk, hist clean
    }

    const unsigned int thr = s_prefix;

    unsigned int cnt = 0;
    float l1 = 0.f;
    float vv[8] = {v0.x, v0.y, v0.z, v0.w, v1.x, v1.y, v1.z, v1.w};
    float mk[8], sx[8];
#pragma unroll
    for (int i = 0; i < 8; i++) {
        bool m = key[i] > thr;            // |x| > thr in float == key > thr in uint
        mk[i] = m ? 1.f : 0.f;
        sx[i] = m ? vv[i] : 0.f;
        if (m) { cnt++; l1 += __uint_as_float(key[i]); }
    }
    *reinterpret_cast<float4*>(&out_mask  [(size_t)row * D_DIM + tid * 4])        = *reinterpret_cast<float4*>(&mk[0]);
    *reinterpret_cast<float4*>(&out_mask  [(size_t)row * D_DIM + 1024 + tid * 4]) = *reinterpret_cast<float4*>(&mk[4]);
    *reinterpret_cast<float4*>(&out_sparse[(size_t)row * D_DIM + tid * 4])        = *reinterpret_cast<float4*>(&sx[0]);
    *reinterpret_cast<float4*>(&out_sparse[(size_t)row * D_DIM + 1024 + tid * 4]) = *reinterpret_cast<float4*>(&sx[4]);

#pragma unroll
    for (int off = 16; off > 0; off >>= 1) {
        cnt += __shfl_xor_sync(0xffffffffu, cnt, off);
        l1  += __shfl_xor_sync(0xffffffffu, l1, off);
    }
    if (lane == 0) { wcnt[wid] = cnt; wl1[wid] = l1; }
    __syncthreads();
    if (tid == 0) {
        unsigned int c = 0; float s = 0.f;
#pragma unroll
        for (int wz = 0; wz < 8; wz++) { c += wcnt[wz]; s += wl1[wz]; }
        out_act[row] = (float)c / (float)D_DIM;
        g_l1row[row] = s;
    }
}

// ---------------- stage 3: deterministic l1 mean -------------------
__global__ void __launch_bounds__(1024) l1_reduce(float* __restrict__ out_l1)
{
    __shared__ float sm[1024];
    const int tid = threadIdx.x;
    float s = 0.f;
    for (int i = tid; i < B_ROWS; i += 1024) s += g_l1row[i];
    sm[tid] = s;
    __syncthreads();
    for (int off = 512; off > 0; off >>= 1) {
        if (tid < off) sm[tid] += sm[tid + off];
        __syncthreads();
    }
    if (tid == 0) out_l1[0] = sm[0] / (float)B_ROWS;
}

// ---------------- launch ------------------------------------------
extern "C" void kernel_launch(void* const* d_in, const int* in_sizes, int n_in,
                              void* d_out, int out_size)
{
    const float* x  = (const float*)d_in[0];
    const float* W1 = (const float*)d_in[1];
    const float* b1 = (const float*)d_in[2];
    const float* W2 = (const float*)d_in[3];
    const float* b2 = (const float*)d_in[4];

    float* out        = (float*)d_out;
    float* out_sparse = out;                                   // [B, D]
    float* out_mask   = out + (size_t)B_ROWS * D_DIM;          // [B, D]
    float* out_sp     = out + 2 * (size_t)B_ROWS * D_DIM;      // [B, 1]
    float* out_act    = out_sp + B_ROWS;                       // [B]
    float* out_l1     = out_act + B_ROWS;                      // [1]

    cudaFuncSetAttribute(gemm_predictor,
                         cudaFuncAttributeMaxDynamicSharedMemorySize, SM_DYN);

    convert_x<<<(B_ROWS * (size_t)D_DIM) / (4 * 256), 256>>>(x);
    convert_w1<<<((size_t)D_DIM * H_DIM) / 256, 256>>>(W1);
    gemm_predictor<<<dim3(4, 128), 256, SM_DYN>>>(b1, W2);
    select_mask_kernel<<<B_ROWS, 256>>>(x, b2, out_sp, out_sparse, out_mask, out_act);
    l1_reduce<<<1, 1024>>>(out_l1);
}

// round 9
// speedup vs baseline: 1.4416x; 1.1762x over previous
#include <cuda_runtime.h>
#include <cuda_fp16.h>
#include <math.h>
#include <stdint.h>

#define B_ROWS 16384
#define D_DIM  2048
#define H_DIM  512
#define NCHUNK 8          // 512 / 64
#define LO_SCALE   2048.0f          // 2^11
#define LO_INV     4.8828125e-4f    // 2^-11

// ------------------------- device scratch -------------------------
__device__ __half g_xs[2ull * B_ROWS * D_DIM];   // x split hi / scaled-lo
__device__ __half g_ws[2ull * H_DIM * D_DIM];    // W1^T split hi / scaled-lo [H,D]
__device__ float  g_partial[B_ROWS * NCHUNK];
__device__ float  g_l1row[B_ROWS];

// ------------------------- helpers --------------------------------
__device__ __forceinline__ uint32_t smem_u32(const void* p) {
    uint32_t a;
    asm("{ .reg .u64 t; cvta.to.shared.u64 t, %1; cvt.u32.u64 %0, t; }" : "=r"(a) : "l"(p));
    return a;
}
__device__ __forceinline__ uint32_t swz128(uint32_t b) { return b ^ ((b >> 3) & 0x70u); }

__device__ __forceinline__ void cp16(uint32_t dst, const void* src) {
    asm volatile("cp.async.cg.shared.global [%0], [%1], 16;" :: "r"(dst), "l"(src) : "memory");
}
__device__ __forceinline__ void cp_commit() {
    asm volatile("cp.async.commit_group;" ::: "memory");
}
template <int N>
__device__ __forceinline__ void cp_wait() {
    asm volatile("cp.async.wait_group %0;" :: "n"(N) : "memory");
}
__device__ __forceinline__ void ldsm4(uint32_t* r, uint32_t addr) {
    asm volatile("ldmatrix.sync.aligned.m8n8.x4.shared.b16 {%0,%1,%2,%3}, [%4];"
                 : "=r"(r[0]), "=r"(r[1]), "=r"(r[2]), "=r"(r[3]) : "r"(addr));
}
__device__ __forceinline__ void mma16816(float* c, const uint32_t* a,
                                         uint32_t b0, uint32_t b1) {
    asm volatile(
        "mma.sync.aligned.m16n8k16.row.col.f32.f16.f16.f32 "
        "{%0,%1,%2,%3}, {%4,%5,%6,%7}, {%8,%9}, {%0,%1,%2,%3};"
        : "+f"(c[0]), "+f"(c[1]), "+f"(c[2]), "+f"(c[3])
        : "r"(a[0]), "r"(a[1]), "r"(a[2]), "r"(a[3]), "r"(b0), "r"(b1));
}

__device__ __forceinline__ void split2s(float f, __half& h, __half& l) {
    h = __float2half_rn(f);
    l = __float2half_rn((f - __half2float(h)) * LO_SCALE);   // scaled: stays normal
}

// --------------- stage 0a: split x into hi / scaled-lo -------------
__global__ void __launch_bounds__(256) convert_x(const float* __restrict__ x)
{
    size_t i4 = ((size_t)blockIdx.x * 256 + threadIdx.x) * 4;
    if (i4 >= (size_t)B_ROWS * D_DIM) return;
    float4 v = *reinterpret_cast<const float4*>(x + i4);
    __half h[4], l[4];
    split2s(v.x, h[0], l[0]);
    split2s(v.y, h[1], l[1]);
    split2s(v.z, h[2], l[2]);
    split2s(v.w, h[3], l[3]);
    const size_t P = (size_t)B_ROWS * D_DIM;
    *reinterpret_cast<uint2*>(&g_xs[i4])     = *reinterpret_cast<uint2*>(h);
    *reinterpret_cast<uint2*>(&g_xs[P + i4]) = *reinterpret_cast<uint2*>(l);
}

// --------------- stage 0b: split + transpose W1 --------------------
__global__ void __launch_bounds__(256) convert_w1(const float* __restrict__ W1)
{
    size_t idx = (size_t)blockIdx.x * 256 + threadIdx.x;   // over [D, H]
    if (idx >= (size_t)D_DIM * H_DIM) return;
    int k = (int)(idx / H_DIM);
    int n = (int)(idx % H_DIM);
    __half h, l;
    split2s(W1[idx], h, l);
    const size_t P = (size_t)H_DIM * D_DIM;
    size_t o = (size_t)n * D_DIM + k;
    g_ws[o]     = h;
    g_ws[P + o] = l;
}

// --------------- stage 1: HMMA split-2 GEMM + fused epilogue -------
// CTA tile: 128(M) x 64(N), BK=64. Grid (8 n-tiles, 128 m-tiles) = 1024 CTAs.
#define SM_DYN (98304 + 1024)

__global__ void __launch_bounds__(256, 1) gemm_predictor(
    const float* __restrict__ b1, const float* __restrict__ W2)
{
    extern __shared__ char smem_raw[];
    __shared__ float red[128][4];

    const uint32_t sb  = (smem_u32(smem_raw) + 1023u) & ~1023u;
    const uint32_t sbB = sb + 65536u;
    const int tid  = threadIdx.x;
    const int lane = tid & 31;
    const int w    = tid >> 5;
    const int wm   = w >> 2;          // 0..1  (M64 rows)
    const int wn   = w & 3;           // 0..3  (N16 cols)
    const int m0   = blockIdx.y * 128;
    const int n0   = blockIdx.x * 64;
    const size_t PX = (size_t)B_ROWS * D_DIM;
    const size_t PW = (size_t)H_DIM * D_DIM;

    float chi[4][2][4];   // hh
    float clo[4][2][4];   // hl + lh (scaled by 2^11)
#pragma unroll
    for (int i = 0; i < 4; i++)
#pragma unroll
        for (int j = 0; j < 2; j++)
#pragma unroll
            for (int e = 0; e < 4; e++) { chi[i][j][e] = 0.f; clo[i][j][e] = 0.f; }

    auto load_tiles = [&](int stage, int kt) {
        const int k0 = kt * 64;
#pragma unroll
        for (int p = 0; p < 2; ++p) {
            const __half* asrc = g_xs + (size_t)p * PX;
            const __half* bsrc = g_ws + (size_t)p * PW;
            const uint32_t abase = sb  + (uint32_t)(stage * 2 + p) * 16384u;
            const uint32_t bbase = sbB + (uint32_t)(stage * 2 + p) * 8192u;
#pragma unroll
            for (int i = 0; i < 4; ++i) {          // A: 128 rows
                int u = tid + i * 256;
                int row = u >> 3, cc = u & 7;
                uint32_t soff = swz128((uint32_t)(row * 128 + cc * 16));
                cp16(abase + soff, asrc + (size_t)(m0 + row) * D_DIM + k0 + cc * 8);
            }
#pragma unroll
            for (int i = 0; i < 2; ++i) {          // B: 64 rows
                int u = tid + i * 256;
                int row = u >> 3, cc = u & 7;
                uint32_t soff = swz128((uint32_t)(row * 128 + cc * 16));
                cp16(bbase + soff, bsrc + (size_t)(n0 + row) * D_DIM + k0 + cc * 8);
            }
        }
    };

    auto compute = [&](int stage) {
        const uint32_t A0 = sb  + (uint32_t)(stage * 2 + 0) * 16384u;
        const uint32_t A1 = sb  + (uint32_t)(stage * 2 + 1) * 16384u;
        const uint32_t B0 = sbB + (uint32_t)(stage * 2 + 0) * 8192u;
        const uint32_t B1 = sbB + (uint32_t)(stage * 2 + 1) * 8192u;
#pragma unroll
        for (int s = 0; s < 4; ++s) {
            const int chunk = (s * 2 + (lane >> 4)) * 16;
            uint32_t brh[4], brl[4];
            {
                int row = wn * 16 + (lane & 15);
                uint32_t off = swz128((uint32_t)(row * 128 + chunk));
                ldsm4(brh, B0 + off);
                ldsm4(brl, B1 + off);
            }
#pragma unroll
            for (int mt = 0; mt < 4; ++mt) {
                int row = wm * 64 + mt * 16 + (lane & 15);
                uint32_t off = swz128((uint32_t)(row * 128 + chunk));
                uint32_t ah[4], al[4];
                ldsm4(ah, A0 + off);
                ldsm4(al, A1 + off);
#pragma unroll
                for (int nt = 0; nt < 2; ++nt) {
                    const uint32_t bh0 = brh[nt], bh1 = brh[nt + 2];
                    const uint32_t bl0 = brl[nt], bl1 = brl[nt + 2];
                    mma16816(chi[mt][nt], ah, bh0, bh1);   // hh
                    mma16816(clo[mt][nt], ah, bl0, bl1);   // hl (x2^11)
                    mma16816(clo[mt][nt], al, bh0, bh1);   // lh (x2^11)
                }
            }
        }
    };

    load_tiles(0, 0);
    cp_commit();
    for (int kt = 0; kt < 32; ++kt) {
        if (kt + 1 < 32) {
            load_tiles((kt + 1) & 1, kt + 1);
            cp_commit();
            cp_wait<1>();
        } else {
            cp_wait<0>();
        }
        __syncthreads();
        compute(kt & 1);
        __syncthreads();
    }

    // epilogue: relu((chi + clo*2^-11) + b1) dot W2 over 64 cols -> partial
#pragma unroll
    for (int mt = 0; mt < 4; ++mt) {
#pragma unroll
        for (int h = 0; h < 2; ++h) {
            float p = 0.f;
#pragma unroll
            for (int nt = 0; nt < 2; ++nt)
#pragma unroll
                for (int e = 0; e < 2; ++e) {
                    int col = n0 + wn * 16 + nt * 8 + (lane & 3) * 2 + e;
                    float v = fmaf(clo[mt][nt][h * 2 + e], LO_INV,
                                   chi[mt][nt][h * 2 + e]) + b1[col];
                    v = fmaxf(v, 0.f);
                    p = fmaf(v, W2[col], p);
                }
            p += __shfl_xor_sync(0xffffffffu, p, 1);
            p += __shfl_xor_sync(0xffffffffu, p, 2);
            if ((lane & 3) == 0) {
                int row = wm * 64 + mt * 16 + (lane >> 2) + 8 * h;
                red[row][wn] = p;
            }
        }
    }
    __syncthreads();
    if (tid < 128) {
        float s = red[tid][0] + red[tid][1] + red[tid][2] + red[tid][3];
        g_partial[(size_t)(m0 + tid) * NCHUNK + blockIdx.x] = s;
    }
}

// ------- stage 2: fused sparsity + exact radix select --------------
// Register-resident keys, 4 passes of 8 bits, 256-bin hist (1KB smem).
__global__ void __launch_bounds__(256) select_mask_kernel(
    const float* __restrict__ x, const float* __restrict__ b2,
    float* __restrict__ out_sp,
    float* __restrict__ out_sparse, float* __restrict__ out_mask,
    float* __restrict__ out_act)
{
    __shared__ unsigned int hist[256];
    __shared__ unsigned int wsum[8];
    __shared__ float        wl1[8];
    __shared__ unsigned int wcnt[8];
    __shared__ unsigned int s_prefix, s_kk;

    const int row  = blockIdx.x;
    const int tid  = threadIdx.x;
    const int lane = tid & 31;
    const int wid  = tid >> 5;
    const float* xr = x + (size_t)row * D_DIM;

    // x register-resident: 8 elements per thread (2 x float4, coalesced)
    float4 v0 = *reinterpret_cast<const float4*>(&xr[tid * 4]);
    float4 v1 = *reinterpret_cast<const float4*>(&xr[1024 + tid * 4]);
    unsigned int key[8];
    key[0] = __float_as_uint(fabsf(v0.x));
    key[1] = __float_as_uint(fabsf(v0.y));
    key[2] = __float_as_uint(fabsf(v0.z));
    key[3] = __float_as_uint(fabsf(v0.w));
    key[4] = __float_as_uint(fabsf(v1.x));
    key[5] = __float_as_uint(fabsf(v1.y));
    key[6] = __float_as_uint(fabsf(v1.z));
    key[7] = __float_as_uint(fabsf(v1.w));

    if (tid == 0) {
        // inline sparsity predictor tail: sum partials -> sigmoid -> k
        float s = b2[0];
#pragma unroll
        for (int cc = 0; cc < NCHUNK; cc++) s += g_partial[(size_t)row * NCHUNK + cc];
        float sig = 1.f / (1.f + expf(-s));
        float sp  = 0.05f + 0.25f * sig;
        out_sp[row] = sp;
        int k = (int)rintf((float)D_DIM * (1.f - sp));   // round half-even
        s_prefix = 0u;
        s_kk = (unsigned int)((k < 1) ? 1 : k);
    }
    hist[tid] = 0u;
    __syncthreads();

#pragma unroll
    for (int shift = 24; shift >= 0; shift -= 8) {
        const unsigned int prefix = s_prefix;
        const unsigned int kcur   = s_kk;
        const unsigned int himask = (shift == 24) ? 0u : (0xFFFFFFFFu << (shift + 8));
#pragma unroll
        for (int i = 0; i < 8; i++) {
            if ((key[i] & himask) == prefix)
                atomicAdd(&hist[(key[i] >> shift) & 255u], 1u);
        }
        __syncthreads();
        const unsigned int own = hist[tid];
        // warp inclusive scan
        unsigned int v = own;
#pragma unroll
        for (int off = 1; off < 32; off <<= 1) {
            unsigned int t = __shfl_up_sync(0xffffffffu, v, off);
            if (lane >= off) v += t;
        }
        if (lane == 31) wsum[wid] = v;
        __syncthreads();
        if (tid < 8) {
            unsigned int ws = wsum[tid];
#pragma unroll
            for (int off = 1; off < 8; off <<= 1) {
                unsigned int t = __shfl_up_sync(0xffu, ws, off, 8);
                if (tid >= off) ws += t;
            }
            wsum[tid] = ws;
        }
        __syncthreads();
        const unsigned int cum  = v + (wid ? wsum[wid - 1] : 0u);
        const unsigned int prev = cum - own;
        if (cum >= kcur && prev < kcur) {
            s_prefix = prefix | ((unsigned int)tid << shift);
            s_kk     = kcur - prev;
        }
        hist[tid] = 0u;          // re-zero for next pass
        __syncthreads();         // publishes s_prefix / s_kk
    }

    const unsigned int thr = s_prefix;

    unsigned int cnt = 0;
    float l1 = 0.f;
    float vv[8] = {v0.x, v0.y, v0.z, v0.w, v1.x, v1.y, v1.z, v1.w};
    float mk[8], sx[8];
#pragma unroll
    for (int i = 0; i < 8; i++) {
        bool m = key[i] > thr;            // |x| > thr : identical in uint order
        mk[i] = m ? 1.f : 0.f;
        sx[i] = m ? vv[i] : 0.f;
        if (m) { cnt++; l1 += __uint_as_float(key[i]); }
    }
    *reinterpret_cast<float4*>(&out_mask  [(size_t)row * D_DIM + tid * 4])        = *reinterpret_cast<float4*>(&mk[0]);
    *reinterpret_cast<float4*>(&out_mask  [(size_t)row * D_DIM + 1024 + tid * 4]) = *reinterpret_cast<float4*>(&mk[4]);
    *reinterpret_cast<float4*>(&out_sparse[(size_t)row * D_DIM + tid * 4])        = *reinterpret_cast<float4*>(&sx[0]);
    *reinterpret_cast<float4*>(&out_sparse[(size_t)row * D_DIM + 1024 + tid * 4]) = *reinterpret_cast<float4*>(&sx[4]);

#pragma unroll
    for (int off = 16; off > 0; off >>= 1) {
        cnt += __shfl_xor_sync(0xffffffffu, cnt, off);
        l1  += __shfl_xor_sync(0xffffffffu, l1, off);
    }
    if (lane == 0) { wcnt[wid] = cnt; wl1[wid] = l1; }
    __syncthreads();
    if (tid == 0) {
        unsigned int c = 0; float s = 0.f;
#pragma unroll
        for (int wz = 0; wz < 8; wz++) { c += wcnt[wz]; s += wl1[wz]; }
        out_act[row] = (float)c / (float)D_DIM;
        g_l1row[row] = s;
    }
}

// ---------------- stage 3: deterministic l1 mean -------------------
__global__ void __launch_bounds__(1024) l1_reduce(float* __restrict__ out_l1)
{
    __shared__ float sm[1024];
    const int tid = threadIdx.x;
    float s = 0.f;
    for (int i = tid; i < B_ROWS; i += 1024) s += g_l1row[i];
    sm[tid] = s;
    __syncthreads();
    for (int off = 512; off > 0; off >>= 1) {
        if (tid < off) sm[tid] += sm[tid + off];
        __syncthreads();
    }
    if (tid == 0) out_l1[0] = sm[0] / (float)B_ROWS;
}

// ---------------- launch ------------------------------------------
extern "C" void kernel_launch(void* const* d_in, const int* in_sizes, int n_in,
                              void* d_out, int out_size)
{
    const float* x  = (const float*)d_in[0];
    const float* W1 = (const float*)d_in[1];
    const float* b1 = (const float*)d_in[2];
    const float* W2 = (const float*)d_in[3];
    const float* b2 = (const float*)d_in[4];

    float* out        = (float*)d_out;
    float* out_sparse = out;                                   // [B, D]
    float* out_mask   = out + (size_t)B_ROWS * D_DIM;          // [B, D]
    float* out_sp     = out + 2 * (size_t)B_ROWS * D_DIM;      // [B, 1]
    float* out_act    = out_sp + B_ROWS;                       // [B]
    float* out_l1     = out_act + B_ROWS;                      // [1]

    cudaFuncSetAttribute(gemm_predictor,
                         cudaFuncAttributeMaxDynamicSharedMemorySize, SM_DYN);

    convert_x<<<(B_ROWS * (size_t)D_DIM) / (4 * 256), 256>>>(x);
    convert_w1<<<((size_t)D_DIM * H_DIM) / 256, 256>>>(W1);
    gemm_predictor<<<dim3(8, 128), 256, SM_DYN>>>(b1, W2);
    select_mask_kernel<<<B_ROWS, 256>>>(x, b2, out_sp, out_sparse, out_mask, out_act);
    l1_reduce<<<1, 1024>>>(out_l1);
}

// round 12
// speedup vs baseline: 1.4607x; 1.0132x over previous
#include <cuda_runtime.h>
#include <cuda_fp16.h>
#include <math.h>
#include <stdint.h>

#define B_ROWS 16384
#define D_DIM  2048
#define H_DIM  512
#define NPART  8          // 512 / 64 n-chunks
#define NCHUNKS 4         // batch chunks for pipelining
#define CHUNK_ROWS (B_ROWS / NCHUNKS)        // 4096
#define LO_SCALE   2048.0f          // 2^11
#define LO_INV     4.8828125e-4f    // 2^-11

// ------------------------- device scratch -------------------------
__device__ __half g_xs[2ull * B_ROWS * D_DIM];   // x split hi / scaled-lo
__device__ __half g_ws[2ull * H_DIM * D_DIM];    // W1^T split hi / scaled-lo [H,D]
__device__ float  g_partial[B_ROWS * NPART];
__device__ float  g_l1row[B_ROWS];

// ------------------------- helpers --------------------------------
__device__ __forceinline__ uint32_t smem_u32(const void* p) {
    uint32_t a;
    asm("{ .reg .u64 t; cvta.to.shared.u64 t, %1; cvt.u32.u64 %0, t; }" : "=r"(a) : "l"(p));
    return a;
}
__device__ __forceinline__ uint32_t swz128(uint32_t b) { return b ^ ((b >> 3) & 0x70u); }

__device__ __forceinline__ void cp16(uint32_t dst, const void* src) {
    asm volatile("cp.async.cg.shared.global [%0], [%1], 16;" :: "r"(dst), "l"(src) : "memory");
}
__device__ __forceinline__ void cp_commit() {
    asm volatile("cp.async.commit_group;" ::: "memory");
}
template <int N>
__device__ __forceinline__ void cp_wait() {
    asm volatile("cp.async.wait_group %0;" :: "n"(N) : "memory");
}
__device__ __forceinline__ void ldsm4(uint32_t* r, uint32_t addr) {
    asm volatile("ldmatrix.sync.aligned.m8n8.x4.shared.b16 {%0,%1,%2,%3}, [%4];"
                 : "=r"(r[0]), "=r"(r[1]), "=r"(r[2]), "=r"(r[3]) : "r"(addr));
}
__device__ __forceinline__ void mma16816(float* c, const uint32_t* a,
                                         uint32_t b0, uint32_t b1) {
    asm volatile(
        "mma.sync.aligned.m16n8k16.row.col.f32.f16.f16.f32 "
        "{%0,%1,%2,%3}, {%4,%5,%6,%7}, {%8,%9}, {%0,%1,%2,%3};"
        : "+f"(c[0]), "+f"(c[1]), "+f"(c[2]), "+f"(c[3])
        : "r"(a[0]), "r"(a[1]), "r"(a[2]), "r"(a[3]), "r"(b0), "r"(b1));
}

__device__ __forceinline__ void split2s(float f, __half& h, __half& l) {
    h = __float2half_rn(f);
    l = __float2half_rn((f - __half2float(h)) * LO_SCALE);   // scaled: stays normal
}

// --------------- stage 0a: split x chunk into hi / scaled-lo -------
__global__ void __launch_bounds__(256) convert_x(const float* __restrict__ x,
                                                 int row_base)
{
    size_t base = (size_t)row_base * D_DIM;
    size_t i4 = base + ((size_t)blockIdx.x * 256 + threadIdx.x) * 4;
    float4 v = *reinterpret_cast<const float4*>(x + i4);
    __half h[4], l[4];
    split2s(v.x, h[0], l[0]);
    split2s(v.y, h[1], l[1]);
    split2s(v.z, h[2], l[2]);
    split2s(v.w, h[3], l[3]);
    const size_t P = (size_t)B_ROWS * D_DIM;
    *reinterpret_cast<uint2*>(&g_xs[i4])     = *reinterpret_cast<uint2*>(h);
    *reinterpret_cast<uint2*>(&g_xs[P + i4]) = *reinterpret_cast<uint2*>(l);
}

// --------------- stage 0b: split + transpose W1 --------------------
__global__ void __launch_bounds__(256) convert_w1(const float* __restrict__ W1)
{
    size_t idx = (size_t)blockIdx.x * 256 + threadIdx.x;   // over [D, H]
    if (idx >= (size_t)D_DIM * H_DIM) return;
    int k = (int)(idx / H_DIM);
    int n = (int)(idx % H_DIM);
    __half h, l;
    split2s(W1[idx], h, l);
    const size_t P = (size_t)H_DIM * D_DIM;
    size_t o = (size_t)n * D_DIM + k;
    g_ws[o]     = h;
    g_ws[P + o] = l;
}

// --------------- stage 1: HMMA split-2 GEMM + fused epilogue -------
// CTA tile: 128(M) x 64(N), BK=64. Per chunk grid (8, 32) = 256 CTAs.
#define SM_DYN (98304 + 1024)

__global__ void __launch_bounds__(256, 1) gemm_predictor(
    const float* __restrict__ b1, const float* __restrict__ W2, int mtile_base)
{
    extern __shared__ char smem_raw[];
    __shared__ float red[128][4];

    const uint32_t sb  = (smem_u32(smem_raw) + 1023u) & ~1023u;
    const uint32_t sbB = sb + 65536u;
    const int tid  = threadIdx.x;
    const int lane = tid & 31;
    const int w    = tid >> 5;
    const int wm   = w >> 2;          // 0..1  (M64 rows)
    const int wn   = w & 3;           // 0..3  (N16 cols)
    const int m0   = (mtile_base + blockIdx.y) * 128;
    const int n0   = blockIdx.x * 64;
    const size_t PX = (size_t)B_ROWS * D_DIM;
    const size_t PW = (size_t)H_DIM * D_DIM;

    float chi[4][2][4];   // hh
    float clo[4][2][4];   // hl + lh (scaled by 2^11)
#pragma unroll
    for (int i = 0; i < 4; i++)
#pragma unroll
        for (int j = 0; j < 2; j++)
#pragma unroll
            for (int e = 0; e < 4; e++) { chi[i][j][e] = 0.f; clo[i][j][e] = 0.f; }

    auto load_tiles = [&](int stage, int kt) {
        const int k0 = kt * 64;
#pragma unroll
        for (int p = 0; p < 2; ++p) {
            const __half* asrc = g_xs + (size_t)p * PX;
            const __half* bsrc = g_ws + (size_t)p * PW;
            const uint32_t abase = sb  + (uint32_t)(stage * 2 + p) * 16384u;
            const uint32_t bbase = sbB + (uint32_t)(stage * 2 + p) * 8192u;
#pragma unroll
            for (int i = 0; i < 4; ++i) {          // A: 128 rows
                int u = tid + i * 256;
                int row = u >> 3, cc = u & 7;
                uint32_t soff = swz128((uint32_t)(row * 128 + cc * 16));
                cp16(abase + soff, asrc + (size_t)(m0 + row) * D_DIM + k0 + cc * 8);
            }
#pragma unroll
            for (int i = 0; i < 2; ++i) {          // B: 64 rows
                int u = tid + i * 256;
                int row = u >> 3, cc = u & 7;
                uint32_t soff = swz128((uint32_t)(row * 128 + cc * 16));
                cp16(bbase + soff, bsrc + (size_t)(n0 + row) * D_DIM + k0 + cc * 8);
            }
        }
    };

    auto compute = [&](int stage) {
        const uint32_t A0 = sb  + (uint32_t)(stage * 2 + 0) * 16384u;
        const uint32_t A1 = sb  + (uint32_t)(stage * 2 + 1) * 16384u;
        const uint32_t B0 = sbB + (uint32_t)(stage * 2 + 0) * 8192u;
        const uint32_t B1 = sbB + (uint32_t)(stage * 2 + 1) * 8192u;
#pragma unroll
        for (int s = 0; s < 4; ++s) {
            const int chunk = (s * 2 + (lane >> 4)) * 16;
            uint32_t brh[4], brl[4];
            {
                int row = wn * 16 + (lane & 15);
                uint32_t off = swz128((uint32_t)(row * 128 + chunk));
                ldsm4(brh, B0 + off);
                ldsm4(brl, B1 + off);
            }
#pragma unroll
            for (int mt = 0; mt < 4; ++mt) {
                int row = wm * 64 + mt * 16 + (lane & 15);
                uint32_t off = swz128((uint32_t)(row * 128 + chunk));
                uint32_t ah[4], al[4];
                ldsm4(ah, A0 + off);
                ldsm4(al, A1 + off);
#pragma unroll
                for (int nt = 0; nt < 2; ++nt) {
                    const uint32_t bh0 = brh[nt], bh1 = brh[nt + 2];
                    const uint32_t bl0 = brl[nt], bl1 = brl[nt + 2];
                    mma16816(chi[mt][nt], ah, bh0, bh1);   // hh
                    mma16816(clo[mt][nt], ah, bl0, bl1);   // hl (x2^11)
                    mma16816(clo[mt][nt], al, bh0, bh1);   // lh (x2^11)
                }
            }
        }
    };

    load_tiles(0, 0);
    cp_commit();
    for (int kt = 0; kt < 32; ++kt) {
        if (kt + 1 < 32) {
            load_tiles((kt + 1) & 1, kt + 1);
            cp_commit();
            cp_wait<1>();
        } else {
            cp_wait<0>();
        }
        __syncthreads();
        compute(kt & 1);
        __syncthreads();
    }

    // epilogue: relu((chi + clo*2^-11) + b1) dot W2 over 64 cols -> partial
#pragma unroll
    for (int mt = 0; mt < 4; ++mt) {
#pragma unroll
        for (int h = 0; h < 2; ++h) {
            float p = 0.f;
#pragma unroll
            for (int nt = 0; nt < 2; ++nt)
#pragma unroll
                for (int e = 0; e < 2; ++e) {
                    int col = n0 + wn * 16 + nt * 8 + (lane & 3) * 2 + e;
                    float v = fmaf(clo[mt][nt][h * 2 + e], LO_INV,
                                   chi[mt][nt][h * 2 + e]) + b1[col];
                    v = fmaxf(v, 0.f);
                    p = fmaf(v, W2[col], p);
                }
            p += __shfl_xor_sync(0xffffffffu, p, 1);
            p += __shfl_xor_sync(0xffffffffu, p, 2);
            if ((lane & 3) == 0) {
                int row = wm * 64 + mt * 16 + (lane >> 2) + 8 * h;
                red[row][wn] = p;
            }
        }
    }
    __syncthreads();
    if (tid < 128) {
        float s = red[tid][0] + red[tid][1] + red[tid][2] + red[tid][3];
        g_partial[(size_t)(m0 + tid) * NPART + blockIdx.x] = s;
    }
}

// ------- stage 2: fused sparsity + exact radix select --------------
// Register-resident keys, 4 passes of 8 bits, 256-bin hist.
__global__ void __launch_bounds__(256) select_mask_kernel(
    const float* __restrict__ x, const float* __restrict__ b2,
    float* __restrict__ out_sp,
    float* __restrict__ out_sparse, float* __restrict__ out_mask,
    float* __restrict__ out_act, int row_base)
{
    __shared__ unsigned int hist[256];
    __shared__ unsigned int wsum[8];
    __shared__ float        wl1[8];
    __shared__ unsigned int wcnt[8];
    __shared__ unsigned int s_prefix, s_kk;

    const int row  = row_base + blockIdx.x;
    const int tid  = threadIdx.x;
    const int lane = tid & 31;
    const int wid  = tid >> 5;
    const float* xr = x + (size_t)row * D_DIM;

    // x register-resident: 8 elements per thread (2 x float4, coalesced)
    float4 v0 = *reinterpret_cast<const float4*>(&xr[tid * 4]);
    float4 v1 = *reinterpret_cast<const float4*>(&xr[1024 + tid * 4]);
    unsigned int key[8];
    key[0] = __float_as_uint(fabsf(v0.x));
    key[1] = __float_as_uint(fabsf(v0.y));
    key[2] = __float_as_uint(fabsf(v0.z));
    key[3] = __float_as_uint(fabsf(v0.w));
    key[4] = __float_as_uint(fabsf(v1.x));
    key[5] = __float_as_uint(fabsf(v1.y));
    key[6] = __float_as_uint(fabsf(v1.z));
    key[7] = __float_as_uint(fabsf(v1.w));

    if (tid == 0) {
        float s = b2[0];
#pragma unroll
        for (int cc = 0; cc < NPART; cc++) s += g_partial[(size_t)row * NPART + cc];
        float sig = 1.f / (1.f + expf(-s));
        float sp  = 0.05f + 0.25f * sig;
        out_sp[row] = sp;
        int k = (int)rintf((float)D_DIM * (1.f - sp));   // round half-even
        s_prefix = 0u;
        s_kk = (unsigned int)((k < 1) ? 1 : k);
    }
    hist[tid] = 0u;
    __syncthreads();

#pragma unroll
    for (int shift = 24; shift >= 0; shift -= 8) {
        const unsigned int prefix = s_prefix;
        const unsigned int kcur   = s_kk;
        const unsigned int himask = (shift == 24) ? 0u : (0xFFFFFFFFu << (shift + 8));
#pragma unroll
        for (int i = 0; i < 8; i++) {
            if ((key[i] & himask) == prefix)
                atomicAdd(&hist[(key[i] >> shift) & 255u], 1u);
        }
        __syncthreads();
        const unsigned int own = hist[tid];
        unsigned int v = own;
#pragma unroll
        for (int off = 1; off < 32; off <<= 1) {
            unsigned int t = __shfl_up_sync(0xffffffffu, v, off);
            if (lane >= off) v += t;
        }
        if (lane == 31) wsum[wid] = v;
        __syncthreads();
        if (tid < 8) {
            unsigned int ws = wsum[tid];
#pragma unroll
            for (int off = 1; off < 8; off <<= 1) {
                unsigned int t = __shfl_up_sync(0xffu, ws, off, 8);
                if (tid >= off) ws += t;
            }
            wsum[tid] = ws;
        }
        __syncthreads();
        const unsigned int cum  = v + (wid ? wsum[wid - 1] : 0u);
        const unsigned int prev = cum - own;
        if (cum >= kcur && prev < kcur) {
            s_prefix = prefix | ((unsigned int)tid << shift);
            s_kk     = kcur - prev;
        }
        hist[tid] = 0u;
        __syncthreads();
    }

    const unsigned int thr = s_prefix;

    unsigned int cnt = 0;
    float l1 = 0.f;
    float vv[8] = {v0.x, v0.y, v0.z, v0.w, v1.x, v1.y, v1.z, v1.w};
    float mk[8], sx[8];
#pragma unroll
    for (int i = 0; i < 8; i++) {
        bool m = key[i] > thr;
        mk[i] = m ? 1.f : 0.f;
        sx[i] = m ? vv[i] : 0.f;
        if (m) { cnt++; l1 += __uint_as_float(key[i]); }
    }
    *reinterpret_cast<float4*>(&out_mask  [(size_t)row * D_DIM + tid * 4])        = *reinterpret_cast<float4*>(&mk[0]);
    *reinterpret_cast<float4*>(&out_mask  [(size_t)row * D_DIM + 1024 + tid * 4]) = *reinterpret_cast<float4*>(&mk[4]);
    *reinterpret_cast<float4*>(&out_sparse[(size_t)row * D_DIM + tid * 4])        = *reinterpret_cast<float4*>(&sx[0]);
    *reinterpret_cast<float4*>(&out_sparse[(size_t)row * D_DIM + 1024 + tid * 4]) = *reinterpret_cast<float4*>(&sx[4]);

#pragma unroll
    for (int off = 16; off > 0; off >>= 1) {
        cnt += __shfl_xor_sync(0xffffffffu, cnt, off);
        l1  += __shfl_xor_sync(0xffffffffu, l1, off);
    }
    if (lane == 0) { wcnt[wid] = cnt; wl1[wid] = l1; }
    __syncthreads();
    if (tid == 0) {
        unsigned int c = 0; float s = 0.f;
#pragma unroll
        for (int wz = 0; wz < 8; wz++) { c += wcnt[wz]; s += wl1[wz]; }
        out_act[row] = (float)c / (float)D_DIM;
        g_l1row[row] = s;
    }
}

// ---------------- stage 3: deterministic l1 mean -------------------
__global__ void __launch_bounds__(1024) l1_reduce(float* __restrict__ out_l1)
{
    __shared__ float sm[1024];
    const int tid = threadIdx.x;
    float s = 0.f;
    for (int i = tid; i < B_ROWS; i += 1024) s += g_l1row[i];
    sm[tid] = s;
    __syncthreads();
    for (int off = 512; off > 0; off >>= 1) {
        if (tid < off) sm[tid] += sm[tid + off];
        __syncthreads();
    }
    if (tid == 0) out_l1[0] = sm[0] / (float)B_ROWS;
}

// ------------- streams/events (pre-main static init) ---------------
static cudaStream_t g_sG, g_sS;               // gemm lane, select lane
static cudaEvent_t  g_evX[NCHUNKS];           // convert_x(ci) done
static cudaEvent_t  g_evG[NCHUNKS];           // gemm(ci) done
static cudaEvent_t  g_evS;                    // last select done
static const bool g_res_init = [](){
    cudaStreamCreateWithFlags(&g_sG, cudaStreamNonBlocking);
    cudaStreamCreateWithFlags(&g_sS, cudaStreamNonBlocking);
    for (int i = 0; i < NCHUNKS; i++) {
        cudaEventCreateWithFlags(&g_evX[i], cudaEventDisableTiming);
        cudaEventCreateWithFlags(&g_evG[i], cudaEventDisableTiming);
    }
    cudaEventCreateWithFlags(&g_evS, cudaEventDisableTiming);
    return true;
}();

// ---------------- launch: 3-lane chunk pipeline --------------------
extern "C" void kernel_launch(void* const* d_in, const int* in_sizes, int n_in,
                              void* d_out, int out_size)
{
    const float* x  = (const float*)d_in[0];
    const float* W1 = (const float*)d_in[1];
    const float* b1 = (const float*)d_in[2];
    const float* W2 = (const float*)d_in[3];
    const float* b2 = (const float*)d_in[4];

    float* out        = (float*)d_out;
    float* out_sparse = out;                                   // [B, D]
    float* out_mask   = out + (size_t)B_ROWS * D_DIM;          // [B, D]
    float* out_sp     = out + 2 * (size_t)B_ROWS * D_DIM;      // [B, 1]
    float* out_act    = out_sp + B_ROWS;                       // [B]
    float* out_l1     = out_act + B_ROWS;                      // [1]

    cudaFuncSetAttribute(gemm_predictor,
                         cudaFuncAttributeMaxDynamicSharedMemorySize, SM_DYN);

    cudaStream_t s0 = 0;   // capture-origin (legacy) stream
    const int conv_grid = (CHUNK_ROWS * D_DIM) / (4 * 256);    // 8192

    // lane 0 (origin): weight convert, then x chunks
    convert_w1<<<((size_t)D_DIM * H_DIM) / 256, 256, 0, s0>>>(W1);
    for (int c = 0; c < NCHUNKS; c++) {
        convert_x<<<conv_grid, 256, 0, s0>>>(x, c * CHUNK_ROWS);
        cudaEventRecord(g_evX[c], s0);
    }

    // lane G: gemm per chunk, gated on its convert
    for (int c = 0; c < NCHUNKS; c++) {
        cudaStreamWaitEvent(g_sG, g_evX[c], 0);
        gemm_predictor<<<dim3(8, CHUNK_ROWS / 128), 256, SM_DYN, g_sG>>>(
            b1, W2, c * (CHUNK_ROWS / 128));
        cudaEventRecord(g_evG[c], g_sG);
    }

    // lane S: select per chunk, gated on its gemm
    for (int c = 0; c < NCHUNKS; c++) {
        cudaStreamWaitEvent(g_sS, g_evG[c], 0);
        select_mask_kernel<<<CHUNK_ROWS, 256, 0, g_sS>>>(
            x, b2, out_sp, out_sparse, out_mask, out_act, c * CHUNK_ROWS);
    }
    cudaEventRecord(g_evS, g_sS);

    // rejoin origin, final reduction
    cudaStreamWaitEvent(s0, g_evS, 0);
    l1_reduce<<<1, 1024, 0, s0>>>(out_l1);
}